// round 7
// baseline (speedup 1.0000x reference)
#include <cuda_runtime.h>
#include <cstdint>

#define NN 50000
#define EE 800000
#define F  128
#define WPAD 132            // transposed-weight row stride (floats): conflict-free

// ================= scratch =================
__device__ int   g_cnt[NN];
__device__ int   g_fill[NN];
__device__ int   g_rowptr[NN + 1];
__device__ int   g_csrc[EE];
__device__ float g_cew[EE];
__device__ float g_tmp[(size_t)NN * F];
__device__ float g_h1[(size_t)NN * F];
__device__ float g_h2[(size_t)NN * F];

// ================= CSR build =================
__global__ void k_zero() {
    int i = blockIdx.x * blockDim.x + threadIdx.x;
    if (i < NN) { g_cnt[i] = 0; g_fill[i] = 0; }
}
__global__ void k_hist(const int* __restrict__ dst) {
    int e = blockIdx.x * blockDim.x + threadIdx.x;
    if (e < EE) atomicAdd(&g_cnt[dst[e]], 1);
}
// warp-shuffle block scan, 1024 threads, chunked over NN
__global__ void k_scan() {
    __shared__ int wsum[32];
    const int tid = threadIdx.x, lane = tid & 31, wid = tid >> 5;
    int carry = 0;
    for (int base = 0; base < NN; base += 1024) {
        int idx  = base + tid;
        int orig = (idx < NN) ? g_cnt[idx] : 0;
        int x = orig;
#pragma unroll
        for (int off = 1; off < 32; off <<= 1) {
            int y = __shfl_up_sync(0xffffffffu, x, off);
            if (lane >= off) x += y;
        }
        if (lane == 31) wsum[wid] = x;
        __syncthreads();
        if (wid == 0) {
            int s = wsum[lane];
#pragma unroll
            for (int off = 1; off < 32; off <<= 1) {
                int y = __shfl_up_sync(0xffffffffu, s, off);
                if (lane >= off) s += y;
            }
            wsum[lane] = s;
        }
        __syncthreads();
        int pre = carry + (wid ? wsum[wid - 1] : 0);
        if (idx < NN) g_rowptr[idx] = pre + x - orig;
        carry += wsum[31];
        __syncthreads();
    }
    if (tid == 0) g_rowptr[NN] = carry;
}
__global__ void k_scatter(const int* __restrict__ src, const int* __restrict__ dst,
                          const float* __restrict__ ew) {
    int e = blockIdx.x * blockDim.x + threadIdx.x;
    if (e < EE) {
        int d = dst[e];
        int p = g_rowptr[d] + atomicAdd(&g_fill[d], 1);
        g_csrc[p] = src[e];
        g_cew[p]  = ew[e];
    }
}

// ================= packed-f32x2 helpers =================
__device__ __forceinline__ void fma2(unsigned long long& d,
                                     unsigned long long a, unsigned long long b) {
    asm("fma.rn.f32x2 %0, %1, %2, %3;" : "=l"(d) : "l"(a), "l"(b), "l"(d));
}
__device__ __forceinline__ float2 unpack2(unsigned long long v) {
    float2 f;
    asm("mov.b64 {%0, %1}, %2;" : "=f"(f.x), "=f"(f.y) : "l"(v));
    return f;
}

// ---- shared GEMM helpers: transposed weight load + f32x2 mainloop ----
// 256 threads / 8 warps. warp w owns nodes 8w..8w+7; lane l owns features l+32m.
__device__ __forceinline__ void load_weightsT(const float* __restrict__ W, float* s_w,
                                              int lane, int wid) {
    for (int task = wid; task < 128; task += 8) {
        int m  = task & 3;
        int k0 = (task >> 2) * 4;
        int j  = m * 32 + lane;
        float4 v;
        v.x = W[(k0 + 0) * F + j];
        v.y = W[(k0 + 1) * F + j];
        v.z = W[(k0 + 2) * F + j];
        v.w = W[(k0 + 3) * F + j];
        *reinterpret_cast<float4*>(s_w + j * WPAD + k0) = v;   // conflict-free
    }
}

__device__ __forceinline__ void gemm_tile(unsigned long long acc2[8][4],
                                          const float* s_t, const float* s_w,
                                          int lane, int wid) {
    const float* s_trow[8];
#pragma unroll
    for (int i = 0; i < 8; i++) s_trow[i] = s_t + (8 * wid + i) * F;
    const float* s_wrow[4];
#pragma unroll
    for (int m = 0; m < 4; m++) s_wrow[m] = s_w + (lane + 32 * m) * WPAD;
#pragma unroll 2
    for (int c = 0; c < 32; c++) {
        ulonglong2 w[4];
#pragma unroll
        for (int m = 0; m < 4; m++)
            w[m] = *reinterpret_cast<const ulonglong2*>(s_wrow[m] + c * 4);
#pragma unroll
        for (int i = 0; i < 8; i++) {
            ulonglong2 h = *reinterpret_cast<const ulonglong2*>(s_trow[i] + c * 4);
#pragma unroll
            for (int m = 0; m < 4; m++) {
                fma2(acc2[i][m], h.x, w[m].x);
                fma2(acc2[i][m], h.y, w[m].y);
            }
        }
    }
}

// ================= k_self: tmp = h @ Ws + b (no relu) =================
__global__ void __launch_bounds__(256, 2)
k_self(const float* __restrict__ hin, const float* __restrict__ W,
       const float* __restrict__ b, float* __restrict__ tmp) {
    extern __shared__ float sm[];
    float* s_w = sm;                 // [128][WPAD]
    float* s_t = sm + F * WPAD;      // [64][128]

    const int tid = threadIdx.x, lane = tid & 31, wid = tid >> 5;
    const int nodeBase = blockIdx.x * 64;

    load_weightsT(W, s_w, lane, wid);
    for (int t = tid; t < 64 * 32; t += 256) {
        int n = t >> 5, q = (t & 31) * 4;
        int v = nodeBase + n;
        float4 hv = make_float4(0.f, 0.f, 0.f, 0.f);
        if (v < NN) hv = *reinterpret_cast<const float4*>(hin + (size_t)v * F + q);
        *reinterpret_cast<float4*>(s_t + n * F + q) = hv;
    }
    __syncthreads();

    unsigned long long acc2[8][4];
#pragma unroll
    for (int i = 0; i < 8; i++)
#pragma unroll
        for (int m = 0; m < 4; m++) acc2[i][m] = 0ull;

    gemm_tile(acc2, s_t, s_w, lane, wid);

    float bj[4];
#pragma unroll
    for (int m = 0; m < 4; m++) bj[m] = b[lane + 32 * m];
#pragma unroll
    for (int i = 0; i < 8; i++) {
        int v = nodeBase + 8 * wid + i;
        if (v < NN) {
#pragma unroll
            for (int m = 0; m < 4; m++) {
                float2 f = unpack2(acc2[i][m]);
                tmp[(size_t)v * F + lane + 32 * m] = f.x + f.y + bj[m];
            }
        }
    }
}

// ================= k_neigh: out = relu(tmp + mean_neigh(h) @ Wn) =================
// Fuses the CSR gather: each block gathers neighbor means for its 64 nodes
// directly into smem s_n (no global neigh buffer), then runs the f32x2 GEMM.
__global__ void __launch_bounds__(256, 2)
k_neigh(const float* __restrict__ hin, const float* __restrict__ W,
        const float* __restrict__ tmp, float* __restrict__ hout) {
    extern __shared__ float sm[];
    float* s_w = sm;                 // [128][WPAD]
    float* s_n = sm + F * WPAD;      // [64][128]

    const int tid = threadIdx.x, lane = tid & 31, wid = tid >> 5;
    const int nodeBase = blockIdx.x * 64;

    load_weightsT(W, s_w, lane, wid);

    // gather phase: warp w -> nodes 8w..8w+7, unroll-4 edge loop (MLP ~4)
#pragma unroll 1
    for (int i = 0; i < 8; i++) {
        int n = 8 * wid + i;
        int v = nodeBase + n;
        float4 a0 = make_float4(0.f, 0.f, 0.f, 0.f);
        float4 a1 = make_float4(0.f, 0.f, 0.f, 0.f);
        int deg = 0;
        if (v < NN) {
            int s0 = g_rowptr[v], s1 = g_rowptr[v + 1];
            deg = s1 - s0;
            int e = s0;
            for (; e + 3 < s1; e += 4) {
                int   sa = g_csrc[e],     sb = g_csrc[e + 1];
                int   sc = g_csrc[e + 2], sd = g_csrc[e + 3];
                float wa = g_cew[e],      wb = g_cew[e + 1];
                float wc = g_cew[e + 2],  wd = g_cew[e + 3];
                float4 A = *reinterpret_cast<const float4*>(hin + (size_t)sa * F + lane * 4);
                float4 B = *reinterpret_cast<const float4*>(hin + (size_t)sb * F + lane * 4);
                float4 C = *reinterpret_cast<const float4*>(hin + (size_t)sc * F + lane * 4);
                float4 D = *reinterpret_cast<const float4*>(hin + (size_t)sd * F + lane * 4);
                a0.x += wa * A.x + wb * B.x;  a1.x += wc * C.x + wd * D.x;
                a0.y += wa * A.y + wb * B.y;  a1.y += wc * C.y + wd * D.y;
                a0.z += wa * A.z + wb * B.z;  a1.z += wc * C.z + wd * D.z;
                a0.w += wa * A.w + wb * B.w;  a1.w += wc * C.w + wd * D.w;
            }
            for (; e < s1; e++) {
                int   s  = g_csrc[e];
                float wt = g_cew[e];
                float4 A = *reinterpret_cast<const float4*>(hin + (size_t)s * F + lane * 4);
                a0.x += wt * A.x; a0.y += wt * A.y;
                a0.z += wt * A.z; a0.w += wt * A.w;
            }
        }
        float invd = 1.0f / (float)(deg > 1 ? deg : 1);
        float4 o;
        o.x = (a0.x + a1.x) * invd;
        o.y = (a0.y + a1.y) * invd;
        o.z = (a0.z + a1.z) * invd;
        o.w = (a0.w + a1.w) * invd;
        *reinterpret_cast<float4*>(s_n + n * F + lane * 4) = o;
    }
    __syncthreads();

    unsigned long long acc2[8][4];
#pragma unroll
    for (int i = 0; i < 8; i++)
#pragma unroll
        for (int m = 0; m < 4; m++) acc2[i][m] = 0ull;

    gemm_tile(acc2, s_n, s_w, lane, wid);

#pragma unroll
    for (int i = 0; i < 8; i++) {
        int v = nodeBase + 8 * wid + i;
        if (v < NN) {
#pragma unroll
            for (int m = 0; m < 4; m++) {
                float2 f = unpack2(acc2[i][m]);
                float p  = tmp[(size_t)v * F + lane + 32 * m];
                hout[(size_t)v * F + lane + 32 * m] = fmaxf(p + f.x + f.y, 0.f);
            }
        }
    }
}

// ================= fused lin1+lin2: out[v] = relu(h@W+b) . w2 + b2 =================
__global__ void __launch_bounds__(256, 2)
k_lin(const float* __restrict__ hin, const float* __restrict__ W,
      const float* __restrict__ b, const float* __restrict__ w2,
      const float* __restrict__ b2, float* __restrict__ outv) {
    extern __shared__ float sm[];
    float* s_w = sm;
    float* s_t = sm + F * WPAD;

    const int tid = threadIdx.x, lane = tid & 31, wid = tid >> 5;
    const int nodeBase = blockIdx.x * 64;

    load_weightsT(W, s_w, lane, wid);
    for (int t = tid; t < 64 * 32; t += 256) {
        int n = t >> 5, q = (t & 31) * 4;
        int v = nodeBase + n;
        float4 hv = make_float4(0.f, 0.f, 0.f, 0.f);
        if (v < NN) hv = *reinterpret_cast<const float4*>(hin + (size_t)v * F + q);
        *reinterpret_cast<float4*>(s_t + n * F + q) = hv;
    }
    __syncthreads();

    unsigned long long acc2[8][4];
#pragma unroll
    for (int i = 0; i < 8; i++)
#pragma unroll
        for (int m = 0; m < 4; m++) acc2[i][m] = 0ull;

    gemm_tile(acc2, s_t, s_w, lane, wid);

    float bj[4], w2j[4];
#pragma unroll
    for (int m = 0; m < 4; m++) { bj[m] = b[lane + 32 * m]; w2j[m] = w2[lane + 32 * m]; }
    float bias2 = b2[0];
#pragma unroll
    for (int i = 0; i < 8; i++) {
        float s = 0.f;
#pragma unroll
        for (int m = 0; m < 4; m++) {
            float2 f = unpack2(acc2[i][m]);
            s += fmaxf(f.x + f.y + bj[m], 0.f) * w2j[m];
        }
#pragma unroll
        for (int o = 16; o; o >>= 1) s += __shfl_xor_sync(0xffffffffu, s, o);
        int v = nodeBase + 8 * wid + i;
        if (lane == 0 && v < NN) outv[v] = s + bias2;
    }
}

// ================= launch =================
extern "C" void kernel_launch(void* const* d_in, const int* in_sizes, int n_in,
                              void* d_out, int out_size) {
    const float* inputs = (const float*)d_in[0];
    const float* ew     = (const float*)d_in[1];
    const int*   src    = (const int*)d_in[2];
    const int*   dst    = (const int*)d_in[3];
    const float* ws1 = (const float*)d_in[4];
    const float* wn1 = (const float*)d_in[5];
    const float* b1  = (const float*)d_in[6];
    const float* ws2 = (const float*)d_in[7];
    const float* wn2 = (const float*)d_in[8];
    const float* b2  = (const float*)d_in[9];
    const float* ws3 = (const float*)d_in[10];
    const float* wn3 = (const float*)d_in[11];
    const float* b3  = (const float*)d_in[12];
    const float* wl1 = (const float*)d_in[13];
    const float* bl1 = (const float*)d_in[14];
    const float* wl2 = (const float*)d_in[15];
    const float* bl2 = (const float*)d_in[16];
    float* out = (float*)d_out;

    float *h1, *h2, *tmp;
    cudaGetSymbolAddress((void**)&h1,  g_h1);
    cudaGetSymbolAddress((void**)&h2,  g_h2);
    cudaGetSymbolAddress((void**)&tmp, g_tmp);

    // smem: weight [128][WPAD] + tile [64][128] = 100352 B -> 2 blocks/SM
    const size_t smem = (size_t)(F * WPAD + 64 * F) * sizeof(float);
    cudaFuncSetAttribute((const void*)k_self,  cudaFuncAttributeMaxDynamicSharedMemorySize, (int)smem);
    cudaFuncSetAttribute((const void*)k_neigh, cudaFuncAttributeMaxDynamicSharedMemorySize, (int)smem);
    cudaFuncSetAttribute((const void*)k_lin,   cudaFuncAttributeMaxDynamicSharedMemorySize, (int)smem);

    const int TB = 256;
    k_zero<<<(NN + TB - 1) / TB, TB>>>();
    k_hist<<<(EE + TB - 1) / TB, TB>>>(dst);
    k_scan<<<1, 1024>>>();
    k_scatter<<<(EE + TB - 1) / TB, TB>>>(src, dst, ew);

    const int sageBlocks = (NN + 63) / 64;          // 782

    // layer 1
    k_self <<<sageBlocks, 256, smem>>>(inputs, ws1, b1, tmp);
    k_neigh<<<sageBlocks, 256, smem>>>(inputs, wn1, tmp, h1);
    // layer 2
    k_self <<<sageBlocks, 256, smem>>>(h1, ws2, b2, tmp);
    k_neigh<<<sageBlocks, 256, smem>>>(h1, wn2, tmp, h2);
    // layer 3
    k_self <<<sageBlocks, 256, smem>>>(h2, ws3, b3, tmp);
    k_neigh<<<sageBlocks, 256, smem>>>(h2, wn3, tmp, h1);
    // lin1 + lin2 fused
    k_lin  <<<sageBlocks, 256, smem>>>(h1, wl1, bl1, wl2, bl2, out);
}

// round 8
// speedup vs baseline: 1.1452x; 1.1452x over previous
#include <cuda_runtime.h>
#include <cstdint>

#define NN 50000
#define EE 800000
#define F  128
#define WPAD 132            // transposed-weight row stride (floats): conflict-free

// ================= scratch =================
__device__ int   g_cnt[NN];
__device__ int   g_fill[NN];
__device__ int   g_rowptr[NN + 1];
__device__ int   g_csrc[EE];
__device__ float g_cew[EE];
__device__ float g_neigh[(size_t)NN * F];
__device__ float g_tmp[(size_t)NN * F];
__device__ float g_h1[(size_t)NN * F];
__device__ float g_h2[(size_t)NN * F];

// ================= CSR build =================
__global__ void k_zero() {
    int i = blockIdx.x * blockDim.x + threadIdx.x;
    if (i < NN) { g_cnt[i] = 0; g_fill[i] = 0; }
}
__global__ void k_hist(const int* __restrict__ dst) {
    int e = blockIdx.x * blockDim.x + threadIdx.x;
    if (e < EE) atomicAdd(&g_cnt[dst[e]], 1);
}
__global__ void k_scan() {
    __shared__ int wsum[32];
    const int tid = threadIdx.x, lane = tid & 31, wid = tid >> 5;
    int carry = 0;
    for (int base = 0; base < NN; base += 1024) {
        int idx  = base + tid;
        int orig = (idx < NN) ? g_cnt[idx] : 0;
        int x = orig;
#pragma unroll
        for (int off = 1; off < 32; off <<= 1) {
            int y = __shfl_up_sync(0xffffffffu, x, off);
            if (lane >= off) x += y;
        }
        if (lane == 31) wsum[wid] = x;
        __syncthreads();
        if (wid == 0) {
            int s = wsum[lane];
#pragma unroll
            for (int off = 1; off < 32; off <<= 1) {
                int y = __shfl_up_sync(0xffffffffu, s, off);
                if (lane >= off) s += y;
            }
            wsum[lane] = s;
        }
        __syncthreads();
        int pre = carry + (wid ? wsum[wid - 1] : 0);
        if (idx < NN) g_rowptr[idx] = pre + x - orig;
        carry += wsum[31];
        __syncthreads();
    }
    if (tid == 0) g_rowptr[NN] = carry;
}
__global__ void k_scatter(const int* __restrict__ src, const int* __restrict__ dst,
                          const float* __restrict__ ew) {
    int e = blockIdx.x * blockDim.x + threadIdx.x;
    if (e < EE) {
        int d = dst[e];
        int p = g_rowptr[d] + atomicAdd(&g_fill[d], 1);
        g_csrc[p] = src[e];
        g_cew[p]  = ew[e];
    }
}

// ================= aggregation (gather, warp per node) =================
__global__ void k_agg(const float* __restrict__ hin) {
    int v    = (blockIdx.x * blockDim.x + threadIdx.x) >> 5;
    int lane = threadIdx.x & 31;
    if (v >= NN) return;
    int s0 = g_rowptr[v], s1 = g_rowptr[v + 1];
    float4 a0 = make_float4(0.f, 0.f, 0.f, 0.f);
    float4 a1 = make_float4(0.f, 0.f, 0.f, 0.f);
    int e = s0;
    for (; e + 3 < s1; e += 4) {
        int   sa = g_csrc[e],     sb = g_csrc[e + 1];
        int   sc = g_csrc[e + 2], sd = g_csrc[e + 3];
        float wa = g_cew[e],      wb = g_cew[e + 1];
        float wc = g_cew[e + 2],  wd = g_cew[e + 3];
        float4 A = *reinterpret_cast<const float4*>(hin + (size_t)sa * F + lane * 4);
        float4 B = *reinterpret_cast<const float4*>(hin + (size_t)sb * F + lane * 4);
        float4 C = *reinterpret_cast<const float4*>(hin + (size_t)sc * F + lane * 4);
        float4 D = *reinterpret_cast<const float4*>(hin + (size_t)sd * F + lane * 4);
        a0.x += wa * A.x + wb * B.x;  a1.x += wc * C.x + wd * D.x;
        a0.y += wa * A.y + wb * B.y;  a1.y += wc * C.y + wd * D.y;
        a0.z += wa * A.z + wb * B.z;  a1.z += wc * C.z + wd * D.z;
        a0.w += wa * A.w + wb * B.w;  a1.w += wc * C.w + wd * D.w;
    }
    for (; e < s1; e++) {
        int   s  = g_csrc[e];
        float wt = g_cew[e];
        float4 A = *reinterpret_cast<const float4*>(hin + (size_t)s * F + lane * 4);
        a0.x += wt * A.x; a0.y += wt * A.y;
        a0.z += wt * A.z; a0.w += wt * A.w;
    }
    int deg = s1 - s0;
    float invd = 1.0f / (float)(deg > 1 ? deg : 1);
    float4 o;
    o.x = (a0.x + a1.x) * invd;
    o.y = (a0.y + a1.y) * invd;
    o.z = (a0.z + a1.z) * invd;
    o.w = (a0.w + a1.w) * invd;
    *reinterpret_cast<float4*>(g_neigh + (size_t)v * F + lane * 4) = o;
}

// ================= packed-f32x2 helpers =================
__device__ __forceinline__ void fma2(unsigned long long& d,
                                     unsigned long long a, unsigned long long b) {
    asm("fma.rn.f32x2 %0, %1, %2, %3;" : "=l"(d) : "l"(a), "l"(b), "l"(d));
}
__device__ __forceinline__ float2 unpack2(unsigned long long v) {
    float2 f;
    asm("mov.b64 {%0, %1}, %2;" : "=f"(f.x), "=f"(f.y) : "l"(v));
    return f;
}

// ---- shared GEMM helpers (256 threads / 8 warps; warp w: nodes 8w..8w+7,
//      lane l: features l+32m) ----
__device__ __forceinline__ void load_weightsT(const float* __restrict__ W, float* s_w,
                                              int lane, int wid) {
    for (int task = wid; task < 128; task += 8) {
        int m  = task & 3;
        int k0 = (task >> 2) * 4;
        int j  = m * 32 + lane;
        float4 v;
        v.x = W[(k0 + 0) * F + j];
        v.y = W[(k0 + 1) * F + j];
        v.z = W[(k0 + 2) * F + j];
        v.w = W[(k0 + 3) * F + j];
        *reinterpret_cast<float4*>(s_w + j * WPAD + k0) = v;   // conflict-free
    }
}
__device__ __forceinline__ void stage_tile(const float* __restrict__ src, float* s_t,
                                           int nodeBase, int tid) {
    for (int t = tid; t < 64 * 32; t += 256) {
        int n = t >> 5, q = (t & 31) * 4;
        int v = nodeBase + n;
        float4 hv = make_float4(0.f, 0.f, 0.f, 0.f);
        if (v < NN) hv = *reinterpret_cast<const float4*>(src + (size_t)v * F + q);
        *reinterpret_cast<float4*>(s_t + n * F + q) = hv;
    }
}
__device__ __forceinline__ void gemm_tile(unsigned long long acc2[8][4],
                                          const float* s_t, const float* s_w,
                                          int lane, int wid) {
    const float* s_trow[8];
#pragma unroll
    for (int i = 0; i < 8; i++) s_trow[i] = s_t + (8 * wid + i) * F;
    const float* s_wrow[4];
#pragma unroll
    for (int m = 0; m < 4; m++) s_wrow[m] = s_w + (lane + 32 * m) * WPAD;
#pragma unroll 2
    for (int c = 0; c < 32; c++) {
        ulonglong2 w[4];
#pragma unroll
        for (int m = 0; m < 4; m++)
            w[m] = *reinterpret_cast<const ulonglong2*>(s_wrow[m] + c * 4);
#pragma unroll
        for (int i = 0; i < 8; i++) {
            ulonglong2 h = *reinterpret_cast<const ulonglong2*>(s_trow[i] + c * 4);
#pragma unroll
            for (int m = 0; m < 4; m++) {
                fma2(acc2[i][m], h.x, w[m].x);
                fma2(acc2[i][m], h.y, w[m].y);
            }
        }
    }
}

// ================= k_self: tmp = h @ Ws + b =================
__global__ void __launch_bounds__(256, 2)
k_self(const float* __restrict__ hin, const float* __restrict__ W,
       const float* __restrict__ b, float* __restrict__ tmp) {
    extern __shared__ float sm[];
    float* s_w = sm;
    float* s_t = sm + F * WPAD;
    const int tid = threadIdx.x, lane = tid & 31, wid = tid >> 5;
    const int nodeBase = blockIdx.x * 64;

    load_weightsT(W, s_w, lane, wid);
    stage_tile(hin, s_t, nodeBase, tid);
    __syncthreads();

    unsigned long long acc2[8][4];
#pragma unroll
    for (int i = 0; i < 8; i++)
#pragma unroll
        for (int m = 0; m < 4; m++) acc2[i][m] = 0ull;
    gemm_tile(acc2, s_t, s_w, lane, wid);

    float bj[4];
#pragma unroll
    for (int m = 0; m < 4; m++) bj[m] = b[lane + 32 * m];
#pragma unroll
    for (int i = 0; i < 8; i++) {
        int v = nodeBase + 8 * wid + i;
        if (v < NN) {
#pragma unroll
            for (int m = 0; m < 4; m++) {
                float2 f = unpack2(acc2[i][m]);
                tmp[(size_t)v * F + lane + 32 * m] = f.x + f.y + bj[m];
            }
        }
    }
}

// ================= k_neigh: out = relu(tmp + g_neigh @ Wn) =================
__global__ void __launch_bounds__(256, 2)
k_neigh(const float* __restrict__ W, const float* __restrict__ tmp,
        float* __restrict__ hout) {
    extern __shared__ float sm[];
    float* s_w = sm;
    float* s_t = sm + F * WPAD;
    const int tid = threadIdx.x, lane = tid & 31, wid = tid >> 5;
    const int nodeBase = blockIdx.x * 64;

    load_weightsT(W, s_w, lane, wid);
    stage_tile(g_neigh, s_t, nodeBase, tid);
    __syncthreads();

    unsigned long long acc2[8][4];
#pragma unroll
    for (int i = 0; i < 8; i++)
#pragma unroll
        for (int m = 0; m < 4; m++) acc2[i][m] = 0ull;
    gemm_tile(acc2, s_t, s_w, lane, wid);

#pragma unroll
    for (int i = 0; i < 8; i++) {
        int v = nodeBase + 8 * wid + i;
        if (v < NN) {
#pragma unroll
            for (int m = 0; m < 4; m++) {
                float2 f = unpack2(acc2[i][m]);
                float p  = tmp[(size_t)v * F + lane + 32 * m];
                hout[(size_t)v * F + lane + 32 * m] = fmaxf(p + f.x + f.y, 0.f);
            }
        }
    }
}

// ================= fused lin1+lin2 =================
__global__ void __launch_bounds__(256, 2)
k_lin(const float* __restrict__ hin, const float* __restrict__ W,
      const float* __restrict__ b, const float* __restrict__ w2,
      const float* __restrict__ b2, float* __restrict__ outv) {
    extern __shared__ float sm[];
    float* s_w = sm;
    float* s_t = sm + F * WPAD;
    const int tid = threadIdx.x, lane = tid & 31, wid = tid >> 5;
    const int nodeBase = blockIdx.x * 64;

    load_weightsT(W, s_w, lane, wid);
    stage_tile(hin, s_t, nodeBase, tid);
    __syncthreads();

    unsigned long long acc2[8][4];
#pragma unroll
    for (int i = 0; i < 8; i++)
#pragma unroll
        for (int m = 0; m < 4; m++) acc2[i][m] = 0ull;
    gemm_tile(acc2, s_t, s_w, lane, wid);

    float bj[4], w2j[4];
#pragma unroll
    for (int m = 0; m < 4; m++) { bj[m] = b[lane + 32 * m]; w2j[m] = w2[lane + 32 * m]; }
    float bias2 = b2[0];
#pragma unroll
    for (int i = 0; i < 8; i++) {
        float s = 0.f;
#pragma unroll
        for (int m = 0; m < 4; m++) {
            float2 f = unpack2(acc2[i][m]);
            s += fmaxf(f.x + f.y + bj[m], 0.f) * w2j[m];
        }
#pragma unroll
        for (int o = 16; o; o >>= 1) s += __shfl_xor_sync(0xffffffffu, s, o);
        int v = nodeBase + 8 * wid + i;
        if (lane == 0 && v < NN) outv[v] = s + bias2;
    }
}

// ================= launch (two-stream fork/join, capture-safe) =================
extern "C" void kernel_launch(void* const* d_in, const int* in_sizes, int n_in,
                              void* d_out, int out_size) {
    const float* inputs = (const float*)d_in[0];
    const float* ew     = (const float*)d_in[1];
    const int*   src    = (const int*)d_in[2];
    const int*   dst    = (const int*)d_in[3];
    const float* ws1 = (const float*)d_in[4];
    const float* wn1 = (const float*)d_in[5];
    const float* b1  = (const float*)d_in[6];
    const float* ws2 = (const float*)d_in[7];
    const float* wn2 = (const float*)d_in[8];
    const float* b2  = (const float*)d_in[9];
    const float* ws3 = (const float*)d_in[10];
    const float* wn3 = (const float*)d_in[11];
    const float* b3  = (const float*)d_in[12];
    const float* wl1 = (const float*)d_in[13];
    const float* bl1 = (const float*)d_in[14];
    const float* wl2 = (const float*)d_in[15];
    const float* bl2 = (const float*)d_in[16];
    float* out = (float*)d_out;

    float *h1, *h2, *tmp;
    cudaGetSymbolAddress((void**)&h1,  g_h1);
    cudaGetSymbolAddress((void**)&h2,  g_h2);
    cudaGetSymbolAddress((void**)&tmp, g_tmp);

    const size_t smem = (size_t)(F * WPAD + 64 * F) * sizeof(float); // 100352 B
    static bool inited = false;
    static cudaStream_t s2;
    static cudaEvent_t ev[8];
    if (!inited) {
        cudaFuncSetAttribute((const void*)k_self,  cudaFuncAttributeMaxDynamicSharedMemorySize, (int)smem);
        cudaFuncSetAttribute((const void*)k_neigh, cudaFuncAttributeMaxDynamicSharedMemorySize, (int)smem);
        cudaFuncSetAttribute((const void*)k_lin,   cudaFuncAttributeMaxDynamicSharedMemorySize, (int)smem);
        cudaStreamCreateWithFlags(&s2, cudaStreamNonBlocking);
        for (int i = 0; i < 8; i++) cudaEventCreateWithFlags(&ev[i], cudaEventDisableTiming);
        inited = true;
    }

    const cudaStream_t m = 0;   // same default stream as all prior (captured) rounds
    const int TB = 256;
    const int aggBlocks  = (NN * 32 + TB - 1) / TB;   // 6250
    const int sageBlocks = (NN + 63) / 64;            // 782

    // -------- layer 1: [s2: CSR build + agg1]  ||  [m: self1] --------
    cudaEventRecord(ev[0], m);
    cudaStreamWaitEvent(s2, ev[0], 0);
    k_zero   <<<(NN + TB - 1) / TB, TB, 0, s2>>>();
    k_hist   <<<(EE + TB - 1) / TB, TB, 0, s2>>>(dst);
    k_scan   <<<1, 1024, 0, s2>>>();
    k_scatter<<<(EE + TB - 1) / TB, TB, 0, s2>>>(src, dst, ew);
    k_agg    <<<aggBlocks, TB, 0, s2>>>(inputs);
    k_self   <<<sageBlocks, 256, smem, m>>>(inputs, ws1, b1, tmp);
    cudaEventRecord(ev[1], s2);
    cudaStreamWaitEvent(m, ev[1], 0);
    k_neigh  <<<sageBlocks, 256, smem, m>>>(wn1, tmp, h1);

    // -------- layer 2: [s2: agg2] || [m: self2] --------
    cudaEventRecord(ev[2], m);
    cudaStreamWaitEvent(s2, ev[2], 0);
    k_agg    <<<aggBlocks, TB, 0, s2>>>(h1);
    k_self   <<<sageBlocks, 256, smem, m>>>(h1, ws2, b2, tmp);
    cudaEventRecord(ev[3], s2);
    cudaStreamWaitEvent(m, ev[3], 0);
    k_neigh  <<<sageBlocks, 256, smem, m>>>(wn2, tmp, h2);

    // -------- layer 3: [s2: agg3] || [m: self3] --------
    cudaEventRecord(ev[4], m);
    cudaStreamWaitEvent(s2, ev[4], 0);
    k_agg    <<<aggBlocks, TB, 0, s2>>>(h2);
    k_self   <<<sageBlocks, 256, smem, m>>>(h2, ws3, b3, tmp);
    cudaEventRecord(ev[5], s2);
    cudaStreamWaitEvent(m, ev[5], 0);
    k_neigh  <<<sageBlocks, 256, smem, m>>>(wn3, tmp, h1);

    // -------- head --------
    k_lin    <<<sageBlocks, 256, smem, m>>>(h1, wl1, bl1, wl2, bl2, out);
}

// round 9
// speedup vs baseline: 1.3149x; 1.1482x over previous
#include <cuda_runtime.h>
#include <cuda_fp16.h>
#include <cstdint>

#define NN 50000
#define EE 800000
#define F  128
#define WPAD 132            // transposed-weight row stride (floats): conflict-free

// ================= scratch =================
__device__ int    g_cnt[NN];
__device__ int    g_fill[NN];
__device__ int    g_rowptr[NN + 1];
__device__ int    g_csrc[EE];
__device__ float  g_cew[EE];
__device__ float  g_neigh[(size_t)NN * F];
__device__ float  g_h1[(size_t)NN * F];
__device__ float  g_h2[(size_t)NN * F];
__device__ __half g_hh[(size_t)NN * F];   // half-precision gather operand

// ================= CSR build =================
__global__ void k_zero() {
    int i = blockIdx.x * blockDim.x + threadIdx.x;
    if (i < NN) { g_cnt[i] = 0; g_fill[i] = 0; }
}
__global__ void k_hist(const int* __restrict__ dst) {
    int e = blockIdx.x * blockDim.x + threadIdx.x;
    if (e < EE) atomicAdd(&g_cnt[dst[e]], 1);
}
__global__ void k_scan() {
    __shared__ int wsum[32];
    const int tid = threadIdx.x, lane = tid & 31, wid = tid >> 5;
    int carry = 0;
    for (int base = 0; base < NN; base += 1024) {
        int idx  = base + tid;
        int orig = (idx < NN) ? g_cnt[idx] : 0;
        int x = orig;
#pragma unroll
        for (int off = 1; off < 32; off <<= 1) {
            int y = __shfl_up_sync(0xffffffffu, x, off);
            if (lane >= off) x += y;
        }
        if (lane == 31) wsum[wid] = x;
        __syncthreads();
        if (wid == 0) {
            int s = wsum[lane];
#pragma unroll
            for (int off = 1; off < 32; off <<= 1) {
                int y = __shfl_up_sync(0xffffffffu, s, off);
                if (lane >= off) s += y;
            }
            wsum[lane] = s;
        }
        __syncthreads();
        int pre = carry + (wid ? wsum[wid - 1] : 0);
        if (idx < NN) g_rowptr[idx] = pre + x - orig;
        carry += wsum[31];
        __syncthreads();
    }
    if (tid == 0) g_rowptr[NN] = carry;
}
__global__ void k_scatter(const int* __restrict__ src, const int* __restrict__ dst,
                          const float* __restrict__ ew) {
    int e = blockIdx.x * blockDim.x + threadIdx.x;
    if (e < EE) {
        int d = dst[e];
        int p = g_rowptr[d] + atomicAdd(&g_fill[d], 1);
        g_csrc[p] = src[e];
        g_cew[p]  = ew[e];
    }
}

// ================= fp32 -> fp16 convert (layer-1 gather operand) =================
__global__ void k_cvt(const float* __restrict__ in) {
    int i = blockIdx.x * blockDim.x + threadIdx.x;      // 800000 tasks of 8 floats
    if (i >= NN * F / 8) return;
    const float4 a = reinterpret_cast<const float4*>(in)[2 * i + 0];
    const float4 b = reinterpret_cast<const float4*>(in)[2 * i + 1];
    __half2 h0 = __floats2half2_rn(a.x, a.y);
    __half2 h1 = __floats2half2_rn(a.z, a.w);
    __half2 h2 = __floats2half2_rn(b.x, b.y);
    __half2 h3 = __floats2half2_rn(b.z, b.w);
    uint4 o;
    o.x = *reinterpret_cast<uint32_t*>(&h0);
    o.y = *reinterpret_cast<uint32_t*>(&h1);
    o.z = *reinterpret_cast<uint32_t*>(&h2);
    o.w = *reinterpret_cast<uint32_t*>(&h3);
    reinterpret_cast<uint4*>(g_hh)[i] = o;
}

// ================= aggregation: gather fp16 h, fp32 accumulate =================
__device__ __forceinline__ float4 ld_h4(int node, int lane) {
    // 4 halves (8 B) at feature offset lane*4
    const uint2 hv = *reinterpret_cast<const uint2*>(g_hh + (size_t)node * F + lane * 4);
    float2 p0 = __half22float2(*reinterpret_cast<const __half2*>(&hv.x));
    float2 p1 = __half22float2(*reinterpret_cast<const __half2*>(&hv.y));
    return make_float4(p0.x, p0.y, p1.x, p1.y);
}

__global__ void k_agg() {
    int v    = (blockIdx.x * blockDim.x + threadIdx.x) >> 5;
    int lane = threadIdx.x & 31;
    if (v >= NN) return;
    int s0 = g_rowptr[v], s1 = g_rowptr[v + 1];
    float4 a0 = make_float4(0.f, 0.f, 0.f, 0.f);
    float4 a1 = make_float4(0.f, 0.f, 0.f, 0.f);
    int e = s0;
    for (; e + 3 < s1; e += 4) {
        int   sa = g_csrc[e],     sb = g_csrc[e + 1];
        int   sc = g_csrc[e + 2], sd = g_csrc[e + 3];
        float wa = g_cew[e],      wb = g_cew[e + 1];
        float wc = g_cew[e + 2],  wd = g_cew[e + 3];
        float4 A = ld_h4(sa, lane);
        float4 B = ld_h4(sb, lane);
        float4 C = ld_h4(sc, lane);
        float4 D = ld_h4(sd, lane);
        a0.x += wa * A.x + wb * B.x;  a1.x += wc * C.x + wd * D.x;
        a0.y += wa * A.y + wb * B.y;  a1.y += wc * C.y + wd * D.y;
        a0.z += wa * A.z + wb * B.z;  a1.z += wc * C.z + wd * D.z;
        a0.w += wa * A.w + wb * B.w;  a1.w += wc * C.w + wd * D.w;
    }
    for (; e < s1; e++) {
        int   s  = g_csrc[e];
        float wt = g_cew[e];
        float4 A = ld_h4(s, lane);
        a0.x += wt * A.x; a0.y += wt * A.y;
        a0.z += wt * A.z; a0.w += wt * A.w;
    }
    int deg = s1 - s0;
    float invd = 1.0f / (float)(deg > 1 ? deg : 1);
    float4 o;
    o.x = (a0.x + a1.x) * invd;
    o.y = (a0.y + a1.y) * invd;
    o.z = (a0.z + a1.z) * invd;
    o.w = (a0.w + a1.w) * invd;
    *reinterpret_cast<float4*>(g_neigh + (size_t)v * F + lane * 4) = o;
}

// ================= packed-f32x2 helpers =================
__device__ __forceinline__ void fma2(unsigned long long& d,
                                     unsigned long long a, unsigned long long b) {
    asm("fma.rn.f32x2 %0, %1, %2, %3;" : "=l"(d) : "l"(a), "l"(b), "l"(d));
}
__device__ __forceinline__ float2 unpack2(unsigned long long v) {
    float2 f;
    asm("mov.b64 {%0, %1}, %2;" : "=f"(f.x), "=f"(f.y) : "l"(v));
    return f;
}

// ================= fused SAGE GEMM (R6 core) =================
// 256 threads / 8 warps; 64-node tile; warp w: nodes 8w..8w+7; lane l: feats l+32m.
// Two sequential passes (self, neigh) reuse s_w/s_t. WH: also write fp16 copy.
template <bool HN, bool DOT, bool WH>
__global__ void __launch_bounds__(256, 2)
k_sage(const float* __restrict__ hin, const float* __restrict__ ws,
       const float* __restrict__ wn, const float* __restrict__ b,
       float* __restrict__ hout,
       const float* __restrict__ w2, const float* __restrict__ b2,
       float* __restrict__ outv) {
    extern __shared__ float sm[];
    float* s_w = sm;                 // [128][WPAD] transposed (reused per pass)
    float* s_t = sm + F * WPAD;      // [64][128] node tile

    const int tid  = threadIdx.x;
    const int lane = tid & 31;
    const int wid  = tid >> 5;
    const int nodeBase = blockIdx.x * 64;
    const int n0 = 8 * wid;

    unsigned long long acc2[8][4];
#pragma unroll
    for (int i = 0; i < 8; i++)
#pragma unroll
        for (int m = 0; m < 4; m++) acc2[i][m] = 0ull;

    const float* s_trow[8];
#pragma unroll
    for (int i = 0; i < 8; i++) s_trow[i] = s_t + (n0 + i) * F;
    const float* s_wrow[4];
#pragma unroll
    for (int m = 0; m < 4; m++) s_wrow[m] = s_w + (lane + 32 * m) * WPAD;

    for (int pass = 0; pass < (HN ? 2 : 1); pass++) {
        const float* W    = (pass == 0) ? ws : wn;
        const float* srcp = (pass == 0) ? hin : g_neigh;
        if (pass) __syncthreads();

        for (int task = wid; task < 128; task += 8) {
            int m  = task & 3;
            int k0 = (task >> 2) * 4;
            int j  = m * 32 + lane;
            float4 v;
            v.x = W[(k0 + 0) * F + j];
            v.y = W[(k0 + 1) * F + j];
            v.z = W[(k0 + 2) * F + j];
            v.w = W[(k0 + 3) * F + j];
            *reinterpret_cast<float4*>(s_w + j * WPAD + k0) = v;   // conflict-free
        }
        for (int t = tid; t < 64 * 32; t += 256) {
            int n = t >> 5, q = (t & 31) * 4;
            int v = nodeBase + n;
            float4 hv = make_float4(0.f, 0.f, 0.f, 0.f);
            if (v < NN) hv = *reinterpret_cast<const float4*>(srcp + (size_t)v * F + q);
            *reinterpret_cast<float4*>(s_t + n * F + q) = hv;
        }
        __syncthreads();

#pragma unroll 2
        for (int c = 0; c < 32; c++) {
            ulonglong2 w[4];
#pragma unroll
            for (int m = 0; m < 4; m++)
                w[m] = *reinterpret_cast<const ulonglong2*>(s_wrow[m] + c * 4);
#pragma unroll
            for (int i = 0; i < 8; i++) {
                ulonglong2 h = *reinterpret_cast<const ulonglong2*>(s_trow[i] + c * 4);
#pragma unroll
                for (int m = 0; m < 4; m++) {
                    fma2(acc2[i][m], h.x, w[m].x);
                    fma2(acc2[i][m], h.y, w[m].y);
                }
            }
        }
    }

    float bj[4];
#pragma unroll
    for (int m = 0; m < 4; m++) bj[m] = b[lane + 32 * m];

    if (!DOT) {
#pragma unroll
        for (int i = 0; i < 8; i++) {
            int v = nodeBase + n0 + i;
            if (v < NN) {
#pragma unroll
                for (int m = 0; m < 4; m++) {
                    float2 f = unpack2(acc2[i][m]);
                    float  r = fmaxf(f.x + f.y + bj[m], 0.f);
                    hout[(size_t)v * F + lane + 32 * m] = r;
                    if (WH) g_hh[(size_t)v * F + lane + 32 * m] = __float2half(r);
                }
            }
        }
    } else {
        float w2j[4];
#pragma unroll
        for (int m = 0; m < 4; m++) w2j[m] = w2[lane + 32 * m];
        float bias2 = b2[0];
#pragma unroll
        for (int i = 0; i < 8; i++) {
            float s = 0.f;
#pragma unroll
            for (int m = 0; m < 4; m++) {
                float2 f = unpack2(acc2[i][m]);
                s += fmaxf(f.x + f.y + bj[m], 0.f) * w2j[m];
            }
#pragma unroll
            for (int o = 16; o; o >>= 1) s += __shfl_xor_sync(0xffffffffu, s, o);
            int v = nodeBase + n0 + i;
            if (lane == 0 && v < NN) outv[v] = s + bias2;
        }
    }
}

// ================= launch =================
extern "C" void kernel_launch(void* const* d_in, const int* in_sizes, int n_in,
                              void* d_out, int out_size) {
    const float* inputs = (const float*)d_in[0];
    const float* ew     = (const float*)d_in[1];
    const int*   src    = (const int*)d_in[2];
    const int*   dst    = (const int*)d_in[3];
    const float* ws1 = (const float*)d_in[4];
    const float* wn1 = (const float*)d_in[5];
    const float* b1  = (const float*)d_in[6];
    const float* ws2 = (const float*)d_in[7];
    const float* wn2 = (const float*)d_in[8];
    const float* b2  = (const float*)d_in[9];
    const float* ws3 = (const float*)d_in[10];
    const float* wn3 = (const float*)d_in[11];
    const float* b3  = (const float*)d_in[12];
    const float* wl1 = (const float*)d_in[13];
    const float* bl1 = (const float*)d_in[14];
    const float* wl2 = (const float*)d_in[15];
    const float* bl2 = (const float*)d_in[16];
    float* out = (float*)d_out;

    float *h1, *h2;
    cudaGetSymbolAddress((void**)&h1, g_h1);
    cudaGetSymbolAddress((void**)&h2, g_h2);

    const size_t smem = (size_t)(F * WPAD + 64 * F) * sizeof(float); // 100352 B
    cudaFuncSetAttribute((const void*)k_sage<true,  false, true>,  cudaFuncAttributeMaxDynamicSharedMemorySize, (int)smem);
    cudaFuncSetAttribute((const void*)k_sage<true,  false, false>, cudaFuncAttributeMaxDynamicSharedMemorySize, (int)smem);
    cudaFuncSetAttribute((const void*)k_sage<false, true,  false>, cudaFuncAttributeMaxDynamicSharedMemorySize, (int)smem);

    const int TB = 256;
    const int aggBlocks  = (NN * 32 + TB - 1) / TB;   // warp per node
    const int sageBlocks = (NN + 63) / 64;            // 782

    // convert layer-1 gather operand + CSR build
    k_cvt    <<<(NN * F / 8 + TB - 1) / TB, TB>>>(inputs);
    k_zero   <<<(NN + TB - 1) / TB, TB>>>();
    k_hist   <<<(EE + TB - 1) / TB, TB>>>(dst);
    k_scan   <<<1, 1024>>>();
    k_scatter<<<(EE + TB - 1) / TB, TB>>>(src, dst, ew);

    // layer 1: gather(fp16 inputs) -> sage (writes h1 fp32 + g_hh fp16)
    k_agg<<<aggBlocks, TB>>>();
    k_sage<true, false, true><<<sageBlocks, 256, smem>>>(inputs, ws1, wn1, b1, h1,
                                                         nullptr, nullptr, nullptr);
    // layer 2
    k_agg<<<aggBlocks, TB>>>();
    k_sage<true, false, true><<<sageBlocks, 256, smem>>>(h1, ws2, wn2, b2, h2,
                                                         nullptr, nullptr, nullptr);
    // layer 3 (no fp16 copy needed)
    k_agg<<<aggBlocks, TB>>>();
    k_sage<true, false, false><<<sageBlocks, 256, smem>>>(h2, ws3, wn3, b3, h1,
                                                          nullptr, nullptr, nullptr);
    // lin1 + lin2 fused
    k_sage<false, true, false><<<sageBlocks, 256, smem>>>(h1, wl1, nullptr, bl1, nullptr,
                                                          wl2, bl2, out);
}